// round 15
// baseline (speedup 1.0000x reference)
#include <cuda_runtime.h>
#include <cuda_fp16.h>
#include <math.h>
#include <stdint.h>

#define BSZ     2
#define SEQ     512
#define DMODEL  768
#define DINNER  1536
#define DSTATE  64
#define NHEADS  24
#define HEADDIM 64
#define CONVDIM 1664            // DINNER + 2*DSTATE
#define DINPROJ 3224            // 2*DINNER + 2*DSTATE + NHEADS
#define NTOK    (BSZ*SEQ)       // 1024
#define DFF     3072
#define LN_EPS  1e-5f
#define LC      64              // scan chunk length
#define NC      (SEQ/LC)        // 8 chunks
#define NSCAN   (2*BSZ*NHEADS)  // 96
#define KSPLIT  4

typedef unsigned long long ull;

// ---------------- scratch (static device globals; no allocation) ----------------
__device__ float  g_zx  [NTOK*DINPROJ];
__device__ float  g_xBC [2*NTOK*CONVDIM];
__device__ float  g_dt  [NTOK*NHEADS];
__device__ float  g_dA  [NTOK*NHEADS];
__device__ float  g_y   [2*NTOK*DINNER];
__device__ float  g_part[KSPLIT*NTOK*DMODEL];  // split-K partials
__device__ float  g_state[NSCAN*NC*4096];
__device__ float  g_cum  [NSCAN*SEQ];
// fp16 activations / weights
__device__ __half g_xnh   [NTOK*DMODEL];
__device__ __half g_gsumh [NTOK*DINNER];
__device__ __half g_mh    [NTOK*DMODEL];
__device__ __half g_ff1h  [NTOK*DFF];
__device__ __half g_w_inproj_h [DINPROJ*DMODEL];
__device__ __half g_w_outproj_h[DMODEL*DINNER];
__device__ __half g_w_ff1_h    [DFF*DMODEL];
__device__ __half g_w_ff2_h    [DMODEL*DFF];

// ---------------- helpers ----------------
__device__ __forceinline__ uint32_t sptr(const void* p) {
    return (uint32_t)__cvta_generic_to_shared(p);
}
__device__ __forceinline__ void ldsm4(uint32_t* r, uint32_t addr) {
    asm volatile("ldmatrix.sync.aligned.m8n8.x4.shared.b16 {%0,%1,%2,%3}, [%4];"
                 : "=r"(r[0]), "=r"(r[1]), "=r"(r[2]), "=r"(r[3]) : "r"(addr));
}
__device__ __forceinline__ void mma16816(float* c, const uint32_t* a, const uint32_t* b) {
    asm volatile("mma.sync.aligned.m16n8k16.row.col.f32.f16.f16.f32 "
                 "{%0,%1,%2,%3}, {%4,%5,%6,%7}, {%8,%9}, {%0,%1,%2,%3};"
                 : "+f"(c[0]), "+f"(c[1]), "+f"(c[2]), "+f"(c[3])
                 : "r"(a[0]), "r"(a[1]), "r"(a[2]), "r"(a[3]), "r"(b[0]), "r"(b[1]));
}
// packed fp32x2 math (FFMA2 — only reachable via PTX)
__device__ __forceinline__ ull pack2(float x, float y) {
    ull r; asm("mov.b64 %0,{%1,%2};" : "=l"(r) : "f"(x), "f"(y)); return r;
}
__device__ __forceinline__ void unpack2(ull v, float& x, float& y) {
    asm("mov.b64 {%0,%1},%2;" : "=f"(x), "=f"(y) : "l"(v));
}
__device__ __forceinline__ ull fma2(ull a, ull b, ull c) {
    ull d; asm("fma.rn.f32x2 %0,%1,%2,%3;" : "=l"(d) : "l"(a), "l"(b), "l"(c)); return d;
}
__device__ __forceinline__ ull mul2(ull a, ull b) {
    ull d; asm("mul.rn.f32x2 %0,%1,%2;" : "=l"(d) : "l"(a), "l"(b)); return d;
}
__device__ __forceinline__ ull add2(ull a, ull b) {
    ull d; asm("add.rn.f32x2 %0,%1,%2;" : "=l"(d) : "l"(a), "l"(b)); return d;
}
// SW128 swizzle for 128-byte (64-half) rows: 16B chunk index XORed with row%8.
__device__ __forceinline__ int swz64(int row, int chunk) {
    return row * 64 + ((chunk ^ (row & 7)) << 3);
}

// ---------------- fp32 -> fp16 convert (8 elems/thread) ----------------
__global__ void f2h_kernel(const float* __restrict__ in, __half* __restrict__ out, int n8) {
    int i = blockIdx.x * blockDim.x + threadIdx.x;
    if (i >= n8) return;
    float4 a = ((const float4*)in)[2 * i];
    float4 b = ((const float4*)in)[2 * i + 1];
    __half2 h[4];
    h[0] = __floats2half2_rn(a.x, a.y);
    h[1] = __floats2half2_rn(a.z, a.w);
    h[2] = __floats2half2_rn(b.x, b.y);
    h[3] = __floats2half2_rn(b.z, b.w);
    *(uint4*)&out[8 * i] = *(uint4*)h;
}

__global__ void f2h_rest_kernel(const float* __restrict__ w1, __half* __restrict__ o1, int n1,
                                const float* __restrict__ w2, __half* __restrict__ o2, int n2,
                                const float* __restrict__ w3, __half* __restrict__ o3, int n3) {
    int i = blockIdx.x * blockDim.x + threadIdx.x;
    const float* in; __half* out; int local;
    if (i < n1)           { in = w1; out = o1; local = i; }
    else if (i < n1 + n2) { in = w2; out = o2; local = i - n1; }
    else if (i < n1 + n2 + n3) { in = w3; out = o3; local = i - n1 - n2; }
    else return;
    float4 a = ((const float4*)in)[2 * local];
    float4 b = ((const float4*)in)[2 * local + 1];
    __half2 h[4];
    h[0] = __floats2half2_rn(a.x, a.y);
    h[1] = __floats2half2_rn(a.z, a.w);
    h[2] = __floats2half2_rn(b.x, b.y);
    h[3] = __floats2half2_rn(b.z, b.w);
    *(uint4*)&out[8 * local] = *(uint4*)h;
}

// ---------------- block reduce (256 threads, two values) ----------------
__device__ __forceinline__ void blockReduce2_256(float& a, float& b) {
    __shared__ float sa[8], sb[8];
    #pragma unroll
    for (int o = 16; o > 0; o >>= 1) {
        a += __shfl_xor_sync(0xffffffffu, a, o);
        b += __shfl_xor_sync(0xffffffffu, b, o);
    }
    int w = threadIdx.x >> 5, l = threadIdx.x & 31;
    if (l == 0) { sa[w] = a; sb[w] = b; }
    __syncthreads();
    if (w == 0) {
        a = (l < 8) ? sa[l] : 0.f;
        b = (l < 8) ? sb[l] : 0.f;
        #pragma unroll
        for (int o = 4; o > 0; o >>= 1) {
            a += __shfl_xor_sync(0xffffffffu, a, o);
            b += __shfl_xor_sync(0xffffffffu, b, o);
        }
        if (l == 0) { sa[0] = a; sb[0] = b; }
    }
    __syncthreads();
    a = sa[0]; b = sb[0];
}

// ---------------- layernorm (fp32 in, fp16 out) ----------------
__global__ void ln_kernel(const float* __restrict__ x, const float* __restrict__ w,
                          const float* __restrict__ b, __half* __restrict__ out, int D) {
    int row = blockIdx.x;
    const float* xr = x + (size_t)row * D;
    float s = 0.f, ss = 0.f;
    for (int c = threadIdx.x; c < D; c += 256) { float v = xr[c]; s += v; ss += v * v; }
    blockReduce2_256(s, ss);
    float mean = s / D;
    float var  = ss / D - mean * mean;
    float r = rsqrtf(var + LN_EPS);
    __half* orow = out + (size_t)row * D;
    for (int c = threadIdx.x; c < D; c += 256)
        orow[c] = __float2half((xr[c] - mean) * r * w[c] + b[c]);
}

// ---------------- sum split-K partials + LN2 -> fp16 ----------------
__global__ void reduce_ln2_kernel(const float* __restrict__ ln2_w,
                                  const float* __restrict__ ln2_b) {
    int row = blockIdx.x;
    __shared__ float v[DMODEL];
    float s = 0.f, ss = 0.f;
    for (int c = threadIdx.x; c < DMODEL; c += 256) {
        float t = 0.f;
        #pragma unroll
        for (int k = 0; k < KSPLIT; k++)
            t += g_part[(size_t)k * NTOK * DMODEL + (size_t)row * DMODEL + c];
        v[c] = t; s += t; ss += t * t;
    }
    blockReduce2_256(s, ss);
    float mean = s / DMODEL;
    float var  = ss / DMODEL - mean * mean;
    float r = rsqrtf(var + LN_EPS);
    __half* orow = g_mh + (size_t)row * DMODEL;
    for (int c = threadIdx.x; c < DMODEL; c += 256)
        orow[c] = __float2half((v[c] - mean) * r * ln2_w[c] + ln2_b[c]);
}

// ---------------- sum split-K partials + bias + residual -> out ----------------
__global__ void reduce_out_kernel(const float* __restrict__ bias,
                                  const float* __restrict__ resid,
                                  float* __restrict__ out) {
    int i = blockIdx.x * blockDim.x + threadIdx.x;    // float4 units
    if (i >= NTOK * DMODEL / 4) return;
    float4 acc = make_float4(0.f, 0.f, 0.f, 0.f);
    #pragma unroll
    for (int k = 0; k < KSPLIT; k++) {
        float4 p = ((const float4*)(g_part + (size_t)k * NTOK * DMODEL))[i];
        acc.x += p.x; acc.y += p.y; acc.z += p.z; acc.w += p.w;
    }
    int n4 = i % (DMODEL / 4);
    float4 bs = ((const float4*)bias)[n4];
    float4 rs = ((const float4*)resid)[i];
    acc.x += bs.x + rs.x; acc.y += bs.y + rs.y;
    acc.z += bs.z + rs.z; acc.w += bs.w + rs.w;
    ((float4*)out)[i] = acc;
}

// ---------------- fp16 tensor-core GEMM: C[M,N] = A[M,K] @ B[N,K]^T ----------------
// BM=64, BN=128, BK=64 (128B rows, SW128), 8 warps (4x2), warp tile 16x64 (MI=1).
// 3-stage cp.async pipeline (72 KB smem), 3 blocks/SM, 6 barriers per K=768.
#define NSTAGE 3
#define BKW    64
template<int BM, int BN, int WGM, int WGN>
__global__ __launch_bounds__(256, 3) void hgemm(
    const __half* __restrict__ A, const __half* __restrict__ B,
    int M, int N, int K,
    float* __restrict__ Cf, __half* __restrict__ Ch,
    const float* __restrict__ bias, const float* __restrict__ resid, int act)
{
    static_assert(WGM * WGN == 8, "8 warps");
    constexpr int WTM = BM / WGM;     // 16
    constexpr int WTN = BN / WGN;     // 64
    constexpr int MI  = WTM / 16;     // 1
    constexpr int NP  = WTN / 16;     // 4
    constexpr int NI  = WTN / 8;      // 8

    extern __shared__ __half smemh[];
    __half* As = smemh;                       // NSTAGE * BM * 64
    __half* Bs = smemh + NSTAGE * BM * BKW;   // NSTAGE * BN * 64

    int tid = threadIdx.x;
    int m0 = blockIdx.y * BM, n0 = blockIdx.x * BN;
    int lane = tid & 31, wid = tid >> 5;
    int wm = wid / WGN, wn = wid % WGN;

    int nsplit = gridDim.z;
    int kc = K / nsplit;
    int kbase = blockIdx.z * kc;
    bool is_split = nsplit > 1;
    if (is_split) Cf += (size_t)blockIdx.z * M * N;

    float c[MI][NI][4];
    #pragma unroll
    for (int mi = 0; mi < MI; mi++)
        #pragma unroll
        for (int ni = 0; ni < NI; ni++)
            #pragma unroll
            for (int r = 0; r < 4; r++) c[mi][ni][r] = 0.f;

    int KT = kc / BKW;

    auto load_stage = [&](int kt, int buf) {
        int k0 = kbase + kt * BKW;
        __half* Ab = As + buf * BM * BKW;
        __half* Bb = Bs + buf * BN * BKW;
        #pragma unroll
        for (int i = 0; i < BM / 32; i++) {        // BM*8 chunks / 256 threads
            int ch = tid + i * 256;
            int row = ch >> 3, cx = ch & 7;
            uint32_t da = sptr(&Ab[swz64(row, cx)]);
            const __half* sa = A + (size_t)(m0 + row) * K + k0 + cx * 8;
            asm volatile("cp.async.cg.shared.global [%0], [%1], 16;\n"
                         :: "r"(da), "l"(sa));
        }
        #pragma unroll
        for (int i = 0; i < BN / 32; i++) {
            int ch = tid + i * 256;
            int row = ch >> 3, cx = ch & 7;
            int gn = n0 + row;
            int valid = gn < N;
            uint32_t db = sptr(&Bb[swz64(row, cx)]);
            const __half* sb = B + (size_t)(valid ? gn : 0) * K + k0 + cx * 8;
            int sz = valid ? 16 : 0;
            asm volatile("cp.async.cg.shared.global [%0], [%1], 16, %2;\n"
                         :: "r"(db), "l"(sb), "r"(sz));
        }
    };

    #pragma unroll
    for (int s = 0; s < NSTAGE - 1; s++) {
        if (s < KT) load_stage(s, s);
        asm volatile("cp.async.commit_group;\n");
    }

    for (int kt = 0; kt < KT; kt++) {
        int buf = kt % NSTAGE;
        asm volatile("cp.async.wait_group %0;\n" :: "n"(NSTAGE - 2));
        __syncthreads();

        __half* Ab = As + buf * BM * BKW;
        __half* Bb = Bs + buf * BN * BKW;
        #pragma unroll
        for (int ks = 0; ks < 4; ks++) {           // 4 x K=16 within BK=64
            uint32_t a[MI][4];
            #pragma unroll
            for (int mi = 0; mi < MI; mi++) {
                int row = wm * WTM + mi * 16 + (lane & 15);
                int chunk = ks * 2 + (lane >> 4);
                ldsm4(a[mi], sptr(&Ab[swz64(row, chunk)]));
            }
            uint32_t b[NI][2];
            #pragma unroll
            for (int np = 0; np < NP; np++) {
                uint32_t t[4];
                int row = wn * WTN + np * 16 + (lane & 7) + ((lane >> 4) & 1) * 8;
                int chunk = ks * 2 + ((lane >> 3) & 1);
                ldsm4(t, sptr(&Bb[swz64(row, chunk)]));
                b[np * 2][0] = t[0]; b[np * 2][1] = t[1];
                b[np * 2 + 1][0] = t[2]; b[np * 2 + 1][1] = t[3];
            }
            #pragma unroll
            for (int mi = 0; mi < MI; mi++)
                #pragma unroll
                for (int ni = 0; ni < NI; ni++)
                    mma16816(c[mi][ni], a[mi], b[ni]);
        }

        int nx = kt + NSTAGE - 1;
        if (nx < KT) load_stage(nx, nx % NSTAGE);
        asm volatile("cp.async.commit_group;\n");
    }

    int gr = lane >> 2, tc = (lane & 3) * 2;
    #pragma unroll
    for (int mi = 0; mi < MI; mi++) {
        #pragma unroll
        for (int ni = 0; ni < NI; ni++) {
            int n = n0 + wn * WTN + ni * 8 + tc;
            if (n < N) {
                #pragma unroll
                for (int h = 0; h < 2; h++) {
                    int m = m0 + wm * WTM + mi * 16 + gr + h * 8;
                    float v0 = c[mi][ni][h * 2];
                    float v1 = c[mi][ni][h * 2 + 1];
                    if (!is_split) {
                        if (bias) { v0 += bias[n]; v1 += bias[n + 1]; }
                        if (act == 1) {
                            v0 = 0.5f * v0 * (1.f + erff(v0 * 0.70710678118654752f));
                            v1 = 0.5f * v1 * (1.f + erff(v1 * 0.70710678118654752f));
                        }
                        if (resid) {
                            v0 += resid[(size_t)m * N + n];
                            v1 += resid[(size_t)m * N + n + 1];
                        }
                        if (Ch) *(__half2*)&Ch[(size_t)m * N + n] = __floats2half2_rn(v0, v1);
                        if (Cf) { float2 o = make_float2(v0, v1); *(float2*)&Cf[(size_t)m * N + n] = o; }
                    } else {
                        float2 o = make_float2(v0, v1);
                        *(float2*)&Cf[(size_t)m * N + n] = o;
                    }
                }
            }
        }
    }
}

// ---------------- tiled conv (both dirs) + SiLU, with fused dt/dA ----------------
#define CT 16
#define CC 128
__global__ __launch_bounds__(256) void conv_silu_tile(const float* __restrict__ w,
                                                      const float* __restrict__ cb,
                                                      const float* __restrict__ dt_bias,
                                                      const float* __restrict__ A_log) {
    int cc = blockIdx.x;
    int tt = blockIdx.y;
    int b  = blockIdx.z;
    int c0 = cc * CC, t0 = tt * CT;
    __shared__ float tile[CT + 6][CC];
    __shared__ float wsh[4][CC];
    __shared__ float bsh[CC];

    if (cc == 0) {
        for (int i = threadIdx.x; i < CT * NHEADS; i += 256) {
            int r = i / NHEADS, h = i % NHEADS;
            int row = b * SEQ + t0 + r;
            float xv = g_zx[(size_t)row * DINPROJ + DINNER + CONVDIM + h] + dt_bias[h];
            float sp = (xv > 20.f) ? xv : log1pf(expf(xv));
            g_dt[(size_t)row * NHEADS + h] = sp;
            g_dA[(size_t)row * NHEADS + h] = expf(-expf(A_log[h]) * sp);
        }
    }

    for (int i = threadIdx.x; i < CC * 4; i += 256) {
        int c = i & (CC - 1), k = i >> 7;
        wsh[k][c] = w[(c0 + c) * 4 + k];
    }
    for (int i = threadIdx.x; i < CC; i += 256) bsh[i] = cb[c0 + i];

    const float* base = g_zx + (size_t)(b * SEQ) * DINPROJ + DINNER + c0;
    for (int i = threadIdx.x; i < (CT + 6) * CC; i += 256) {
        int r = i / CC, c = i % CC;
        int t = t0 - 3 + r;
        tile[r][c] = (t >= 0 && t < SEQ) ? base[(size_t)t * DINPROJ + c] : 0.f;
    }
    __syncthreads();

    for (int i = threadIdx.x; i < CT * CC; i += 256) {
        int r = i / CC, c = i % CC;
        int row = b * SEQ + t0 + r;
        float sf = bsh[c], sb2 = bsh[c];
        #pragma unroll
        for (int k = 0; k < 4; k++) {
            sf  = fmaf(wsh[k][c], tile[r + k][c],     sf);
            sb2 = fmaf(wsh[k][c], tile[r + 6 - k][c], sb2);
        }
        g_xBC[(size_t)row * CONVDIM + c0 + c]          = sf  / (1.f + expf(-sf));
        g_xBC[(size_t)(NTOK + row) * CONVDIM + c0 + c] = sb2 / (1.f + expf(-sb2));
    }
}

// ---------------- scan pass A: per-chunk local scan (h_init = 0) ----------------
__global__ __launch_bounds__(256) void scanA_kernel(const float* __restrict__ D_param) {
    int h = blockIdx.x, b = blockIdx.y;
    int dir = blockIdx.z / NC, chunk = blockIdx.z % NC;
    int idx = (dir * BSZ + b) * NHEADS + h;
    const float* xbc  = g_xBC + (size_t)(dir * NTOK + b * SEQ) * CONVDIM;
    float*       yout = g_y   + (size_t)(dir * NTOK + b * SEQ) * DINNER;
    int tid = threadIdx.x;
    int p = tid >> 2, q = tid & 3, nbase = q * 16;
    int s0 = chunk * LC;

    __shared__ float sdt[LC], sdA[LC];
    __shared__ __align__(16) float sbuf[2][192];

    for (int i = tid; i < LC; i += 256) {
        int t = dir ? (SEQ - 1 - (s0 + i)) : (s0 + i);
        sdt[i] = g_dt[(size_t)(b * SEQ + t) * NHEADS + h];
        sdA[i] = g_dA[(size_t)(b * SEQ + t) * NHEADS + h];
    }

    ull hr2[8];
    #pragma unroll
    for (int i = 0; i < 8; i++) hr2[i] = 0ull;
    float Dp = D_param[h];
    float cum = 1.f;

    auto gload = [&](int s) -> float {
        int t = dir ? (SEQ - 1 - s) : s;
        const float* r = xbc + (size_t)t * CONVDIM;
        if (tid < 64)  return r[h * 64 + tid];
        if (tid < 192) return r[DINNER + (tid - 64)];
        return 0.f;
    };

    float staged = gload(s0);

    for (int sl = 0; sl < LC; sl++) {
        int s = s0 + sl;
        int t = dir ? (SEQ - 1 - s) : s;
        int buf = sl & 1;
        if (tid < 192) sbuf[buf][tid] = staged;
        __syncthreads();
        if (sl + 1 < LC) staged = gload(s + 1);

        float xp  = sbuf[buf][p];
        float dtv = sdt[sl];
        float dAv = sdA[sl];
        float bx  = dtv * xp;
        cum *= dAv;

        ull B2[8], C2[8];
        const longlong2* Bp = (const longlong2*)&sbuf[buf][64 + nbase];
        const longlong2* Cp = (const longlong2*)&sbuf[buf][128 + nbase];
        #pragma unroll
        for (int i = 0; i < 4; i++) {
            longlong2 v = Bp[i]; B2[2 * i] = (ull)v.x; B2[2 * i + 1] = (ull)v.y;
            longlong2 u = Cp[i]; C2[2 * i] = (ull)u.x; C2[2 * i + 1] = (ull)u.y;
        }
        ull bx2 = pack2(bx, bx);
        ull dA2 = pack2(dAv, dAv);
        ull acca = 0ull, accb = 0ull;
        #pragma unroll
        for (int i = 0; i < 8; i += 2) {
            hr2[i]     = fma2(dA2, hr2[i],     mul2(bx2, B2[i]));
            hr2[i + 1] = fma2(dA2, hr2[i + 1], mul2(bx2, B2[i + 1]));
            acca = fma2(hr2[i],     C2[i],     acca);
            accb = fma2(hr2[i + 1], C2[i + 1], accb);
        }
        ull accp = add2(acca, accb);
        float a0, a1; unpack2(accp, a0, a1);
        float acc = a0 + a1;
        acc += __shfl_xor_sync(0xffffffffu, acc, 1);
        acc += __shfl_xor_sync(0xffffffffu, acc, 2);
        if (q == 0) yout[(size_t)t * DINNER + h * 64 + p] = fmaf(Dp, xp, acc);
        if (tid == 0) g_cum[(size_t)idx * SEQ + s] = cum;
    }

    float* st = g_state + ((size_t)idx * NC + chunk) * 4096 + tid * 16;
    #pragma unroll
    for (int i = 0; i < 8; i++) {
        float x0, x1; unpack2(hr2[i], x0, x1);
        st[2 * i] = x0; st[2 * i + 1] = x1;
    }
}

// ---------------- scan pass C: inline combine + correction ----------------
__global__ __launch_bounds__(256) void scanC_kernel() {
    int h = blockIdx.x, b = blockIdx.y;
    int dir = blockIdx.z / (NC - 1), chunk = blockIdx.z % (NC - 1) + 1;
    int idx = (dir * BSZ + b) * NHEADS + h;
    const float* xbc  = g_xBC + (size_t)(dir * NTOK + b * SEQ) * CONVDIM;
    float*       yout = g_y   + (size_t)(dir * NTOK + b * SEQ) * DINNER;
    int tid = threadIdx.x;
    int p = tid >> 2, q = tid & 3, nbase = q * 16;
    int s0 = chunk * LC;

    __shared__ float scum[LC];
    __shared__ __align__(16) float sC[2][64];

    for (int i = tid; i < LC; i += 256)
        scum[i] = g_cum[(size_t)idx * SEQ + s0 + i];

    float hin[16];
    #pragma unroll
    for (int i = 0; i < 16; i++) hin[i] = 0.f;
    for (int j = 0; j < chunk; j++) {
        float P = g_cum[(size_t)idx * SEQ + j * LC + LC - 1];
        const float4* L = (const float4*)(g_state + ((size_t)idx * NC + j) * 4096 + tid * 16);
        #pragma unroll
        for (int i = 0; i < 4; i++) {
            float4 l = L[i];
            hin[4 * i]     = fmaf(P, hin[4 * i],     l.x);
            hin[4 * i + 1] = fmaf(P, hin[4 * i + 1], l.y);
            hin[4 * i + 2] = fmaf(P, hin[4 * i + 2], l.z);
            hin[4 * i + 3] = fmaf(P, hin[4 * i + 3], l.w);
        }
    }

    auto gloadC = [&](int s) -> float {
        int t = dir ? (SEQ - 1 - s) : s;
        if (tid < 64) return xbc[(size_t)t * CONVDIM + DINNER + DSTATE + tid];
        return 0.f;
    };

    float staged = gloadC(s0);

    for (int sl = 0; sl < LC; sl++) {
        int s = s0 + sl;
        int t = dir ? (SEQ - 1 - s) : s;
        int buf = sl & 1;
        if (tid < 64) sC[buf][tid] = staged;
        __syncthreads();
        if (sl + 1 < LC) staged = gloadC(s + 1);

        const float* Cv = &sC[buf][nbase];
        float acc = 0.f;
        #pragma unroll
        for (int i = 0; i < 16; i++) acc = fmaf(Cv[i], hin[i], acc);
        acc += __shfl_xor_sync(0xffffffffu, acc, 1);
        acc += __shfl_xor_sync(0xffffffffu, acc, 2);
        if (q == 0) {
            float* yp = &yout[(size_t)t * DINNER + h * 64 + p];
            *yp = fmaf(scum[sl], acc, *yp);
        }
    }
}

// ---------------- gate with SiLU(z), per-direction RMSNorm, sum dirs (fp16 out) ----------------
__global__ void gate_rms_kernel(const float* __restrict__ norm_w) {
    int row = blockIdx.x;
    __shared__ float gf[DINNER];
    __shared__ float gb[DINNER];
    const float* zr = g_zx + (size_t)row * DINPROJ;
    const float* yf = g_y  + (size_t)row * DINNER;
    const float* yb = g_y  + (size_t)(NTOK + row) * DINNER;
    float ssf = 0.f, ssb = 0.f;
    for (int c = threadIdx.x; c < DINNER; c += 256) {
        float zc = zr[c];
        float sz = zc / (1.f + expf(-zc));
        float a  = yf[c] * sz;
        float bb = yb[c] * sz;
        gf[c] = a; gb[c] = bb;
        ssf += a * a; ssb += bb * bb;
    }
    blockReduce2_256(ssf, ssb);
    float rf = rsqrtf(ssf / DINNER + LN_EPS);
    float rb = rsqrtf(ssb / DINNER + LN_EPS);
    __half* orow = g_gsumh + (size_t)row * DINNER;
    for (int c = threadIdx.x; c < DINNER; c += 256)
        orow[c] = __float2half((gf[c] * rf + gb[c] * rb) * norm_w[c]);
}

// ---------------- launch ----------------
extern "C" void kernel_launch(void* const* d_in, const int* in_sizes, int n_in,
                              void* d_out, int out_size) {
    const float* x         = (const float*)d_in[0];
    const float* in_proj_w = (const float*)d_in[1];
    const float* conv_w    = (const float*)d_in[2];
    const float* conv_b    = (const float*)d_in[3];
    const float* dt_bias   = (const float*)d_in[4];
    const float* A_log     = (const float*)d_in[5];
    const float* D_param   = (const float*)d_in[6];
    const float* norm_w    = (const float*)d_in[7];
    const float* out_proj_w= (const float*)d_in[8];
    const float* ln1_w     = (const float*)d_in[9];
    const float* ln1_b     = (const float*)d_in[10];
    const float* ln2_w     = (const float*)d_in[11];
    const float* ln2_b     = (const float*)d_in[12];
    const float* ff_w1     = (const float*)d_in[13];
    const float* ff_b1     = (const float*)d_in[14];
    const float* ff_w2     = (const float*)d_in[15];
    const float* ff_b2     = (const float*)d_in[16];
    float* out = (float*)d_out;

    void *p_zx, *p_xnh, *p_gsumh, *p_mh, *p_ff1h;
    void *p_wi, *p_wo, *p_w1, *p_w2, *p_part;
    cudaGetSymbolAddress(&p_zx,    g_zx);
    cudaGetSymbolAddress(&p_part,  g_part);
    cudaGetSymbolAddress(&p_xnh,   g_xnh);
    cudaGetSymbolAddress(&p_gsumh, g_gsumh);
    cudaGetSymbolAddress(&p_mh,    g_mh);
    cudaGetSymbolAddress(&p_ff1h,  g_ff1h);
    cudaGetSymbolAddress(&p_wi,    g_w_inproj_h);
    cudaGetSymbolAddress(&p_wo,    g_w_outproj_h);
    cudaGetSymbolAddress(&p_w1,    g_w_ff1_h);
    cudaGetSymbolAddress(&p_w2,    g_w_ff2_h);

    const int smemG = NSTAGE * (64 + 128) * BKW * sizeof(__half);   // 72 KB
    cudaFuncSetAttribute((const void*)hgemm<64,128,4,2>,
                         cudaFuncAttributeMaxDynamicSharedMemorySize, smemG);

    // 1) LN1 -> fp16 xn  (launch 0)
    ln_kernel<<<NTOK, 256>>>(x, ln1_w, ln1_b, (__half*)p_xnh, DMODEL);

    // 2) in_proj weight convert (launch 1)
    {
        int n0 = DINPROJ * DMODEL / 8;
        f2h_kernel<<<(n0 + 255) / 256, 256>>>(in_proj_w, (__half*)p_wi, n0);
    }
    // 3) remaining weights (launch 2)
    {
        int n1 = DMODEL * DINNER / 8;
        int n2 = DFF * DMODEL / 8;
        int n3 = DMODEL * DFF / 8;
        f2h_rest_kernel<<<(n1 + n2 + n3 + 255) / 256, 256>>>(
            out_proj_w, (__half*)p_wo, n1,
            ff_w1, (__half*)p_w1, n2,
            ff_w2, (__half*)p_w2, n3);
    }

    // 4) in_proj GEMM (launch 3 — ncu capture window): 26x16 = 416 blocks
    hgemm<64,128,4,2><<<dim3((DINPROJ + 127) / 128, NTOK / 64), 256, smemG>>>(
        (const __half*)p_xnh, (const __half*)p_wi,
        NTOK, DINPROJ, DMODEL, (float*)p_zx, nullptr, nullptr, nullptr, 0);

    // 5) conv + SiLU (both directions) with fused dt/dA
    conv_silu_tile<<<dim3(CONVDIM / CC, SEQ / CT, BSZ), 256>>>(conv_w, conv_b, dt_bias, A_log);

    // 6) chunked selective scan
    scanA_kernel<<<dim3(NHEADS, BSZ, 2 * NC), 256>>>(D_param);
    scanC_kernel<<<dim3(NHEADS, BSZ, 2 * (NC - 1)), 256>>>();

    // 7) gate + RMSNorm + direction-sum -> fp16
    gate_rms_kernel<<<NTOK, 256>>>(norm_w);

    // 8) out_proj GEMM split-K x4 -> partials: 6x16x4 = 384 blocks
    hgemm<64,128,4,2><<<dim3(DMODEL / 128, NTOK / 64, KSPLIT), 256, smemG>>>(
        (const __half*)p_gsumh, (const __half*)p_wo,
        NTOK, DMODEL, DINNER, (float*)p_part, nullptr, nullptr, nullptr, 0);

    // 9) reduce partials + LN2 -> fp16 m
    reduce_ln2_kernel<<<NTOK, 256>>>(ln2_w, ln2_b);

    // 10) FF1 + bias + GELU -> fp16: 24x16 = 384 blocks
    hgemm<64,128,4,2><<<dim3(DFF / 128, NTOK / 64), 256, smemG>>>(
        (const __half*)p_mh, (const __half*)p_w1,
        NTOK, DFF, DMODEL, nullptr, (__half*)p_ff1h, ff_b1, nullptr, 1);

    // 11) FF2 split-K x4 -> partials: 384 blocks
    hgemm<64,128,4,2><<<dim3(DMODEL / 128, NTOK / 64, KSPLIT), 256, smemG>>>(
        (const __half*)p_ff1h, (const __half*)p_w2,
        NTOK, DMODEL, DFF, (float*)p_part, nullptr, nullptr, nullptr, 0);

    // 12) reduce partials + bias + residual -> out
    reduce_out_kernel<<<(NTOK * DMODEL / 4 + 255) / 256, 256>>>(ff_b2, x, out);
}

// round 16
// speedup vs baseline: 1.5769x; 1.5769x over previous
#include <cuda_runtime.h>
#include <cuda_fp16.h>
#include <math.h>
#include <stdint.h>

#define BSZ     2
#define SEQ     512
#define DMODEL  768
#define DINNER  1536
#define DSTATE  64
#define NHEADS  24
#define HEADDIM 64
#define CONVDIM 1664            // DINNER + 2*DSTATE
#define DINPROJ 3224            // 2*DINNER + 2*DSTATE + NHEADS
#define NTOK    (BSZ*SEQ)       // 1024
#define DFF     3072
#define LN_EPS  1e-5f
#define LC      64              // scan chunk length
#define NC      (SEQ/LC)        // 8 chunks
#define NSCAN   (2*BSZ*NHEADS)  // 96
#define KSPLIT  6

typedef unsigned long long ull;

// ---------------- scratch (static device globals; no allocation) ----------------
__device__ float  g_zx  [NTOK*DINPROJ];
__device__ float  g_xBC [2*NTOK*CONVDIM];
__device__ float  g_dt  [NTOK*NHEADS];
__device__ float  g_dA  [NTOK*NHEADS];
__device__ float  g_y   [2*NTOK*DINNER];
__device__ float  g_part[KSPLIT*NTOK*DMODEL];  // split-K partials
__device__ float  g_state[NSCAN*NC*4096];
__device__ float  g_cum  [NSCAN*SEQ];
// fp16 activations / weights
__device__ __half g_xnh   [NTOK*DMODEL];
__device__ __half g_gsumh [NTOK*DINNER];
__device__ __half g_mh    [NTOK*DMODEL];
__device__ __half g_ff1h  [NTOK*DFF];
__device__ __half g_w_inproj_h [DINPROJ*DMODEL];
__device__ __half g_w_outproj_h[DMODEL*DINNER];
__device__ __half g_w_ff1_h    [DFF*DMODEL];
__device__ __half g_w_ff2_h    [DMODEL*DFF];

// ---------------- helpers ----------------
__device__ __forceinline__ uint32_t sptr(const void* p) {
    return (uint32_t)__cvta_generic_to_shared(p);
}
__device__ __forceinline__ void ldsm4(uint32_t* r, uint32_t addr) {
    asm volatile("ldmatrix.sync.aligned.m8n8.x4.shared.b16 {%0,%1,%2,%3}, [%4];"
                 : "=r"(r[0]), "=r"(r[1]), "=r"(r[2]), "=r"(r[3]) : "r"(addr));
}
__device__ __forceinline__ void mma16816(float* c, const uint32_t* a, const uint32_t* b) {
    asm volatile("mma.sync.aligned.m16n8k16.row.col.f32.f16.f16.f32 "
                 "{%0,%1,%2,%3}, {%4,%5,%6,%7}, {%8,%9}, {%0,%1,%2,%3};"
                 : "+f"(c[0]), "+f"(c[1]), "+f"(c[2]), "+f"(c[3])
                 : "r"(a[0]), "r"(a[1]), "r"(a[2]), "r"(a[3]), "r"(b[0]), "r"(b[1]));
}
// packed fp32x2 math (FFMA2 — only reachable via PTX)
__device__ __forceinline__ ull pack2(float x, float y) {
    ull r; asm("mov.b64 %0,{%1,%2};" : "=l"(r) : "f"(x), "f"(y)); return r;
}
__device__ __forceinline__ void unpack2(ull v, float& x, float& y) {
    asm("mov.b64 {%0,%1},%2;" : "=f"(x), "=f"(y) : "l"(v));
}
__device__ __forceinline__ ull fma2(ull a, ull b, ull c) {
    ull d; asm("fma.rn.f32x2 %0,%1,%2,%3;" : "=l"(d) : "l"(a), "l"(b), "l"(c)); return d;
}
__device__ __forceinline__ ull mul2(ull a, ull b) {
    ull d; asm("mul.rn.f32x2 %0,%1,%2;" : "=l"(d) : "l"(a), "l"(b)); return d;
}
__device__ __forceinline__ ull add2(ull a, ull b) {
    ull d; asm("add.rn.f32x2 %0,%1,%2;" : "=l"(d) : "l"(a), "l"(b)); return d;
}
// SW128 swizzle for 128-byte (64-half) rows: 16B chunk index XORed with row%8.
__device__ __forceinline__ int swz64(int row, int chunk) {
    return row * 64 + ((chunk ^ (row & 7)) << 3);
}

// ---------------- fused fp32 -> fp16 convert for all 4 weights ----------------
__global__ void f2h_all_kernel(const float* __restrict__ w0, __half* __restrict__ o0, int n0,
                               const float* __restrict__ w1, __half* __restrict__ o1, int n1,
                               const float* __restrict__ w2, __half* __restrict__ o2, int n2,
                               const float* __restrict__ w3, __half* __restrict__ o3, int n3) {
    int i = blockIdx.x * blockDim.x + threadIdx.x;
    const float* in; __half* out; int local;
    if (i < n0)                { in = w0; out = o0; local = i; }
    else if (i < n0 + n1)      { in = w1; out = o1; local = i - n0; }
    else if (i < n0 + n1 + n2) { in = w2; out = o2; local = i - n0 - n1; }
    else if (i < n0 + n1 + n2 + n3) { in = w3; out = o3; local = i - n0 - n1 - n2; }
    else return;
    float4 a = ((const float4*)in)[2 * local];
    float4 b = ((const float4*)in)[2 * local + 1];
    __half2 h[4];
    h[0] = __floats2half2_rn(a.x, a.y);
    h[1] = __floats2half2_rn(a.z, a.w);
    h[2] = __floats2half2_rn(b.x, b.y);
    h[3] = __floats2half2_rn(b.z, b.w);
    *(uint4*)&out[8 * local] = *(uint4*)h;
}

// ---------------- block reduce (256 threads, two values) ----------------
__device__ __forceinline__ void blockReduce2_256(float& a, float& b) {
    __shared__ float sa[8], sb[8];
    #pragma unroll
    for (int o = 16; o > 0; o >>= 1) {
        a += __shfl_xor_sync(0xffffffffu, a, o);
        b += __shfl_xor_sync(0xffffffffu, b, o);
    }
    int w = threadIdx.x >> 5, l = threadIdx.x & 31;
    if (l == 0) { sa[w] = a; sb[w] = b; }
    __syncthreads();
    if (w == 0) {
        a = (l < 8) ? sa[l] : 0.f;
        b = (l < 8) ? sb[l] : 0.f;
        #pragma unroll
        for (int o = 4; o > 0; o >>= 1) {
            a += __shfl_xor_sync(0xffffffffu, a, o);
            b += __shfl_xor_sync(0xffffffffu, b, o);
        }
        if (l == 0) { sa[0] = a; sb[0] = b; }
    }
    __syncthreads();
    a = sa[0]; b = sb[0];
}

// ---------------- layernorm (fp32 in, fp16 out) ----------------
__global__ void ln_kernel(const float* __restrict__ x, const float* __restrict__ w,
                          const float* __restrict__ b, __half* __restrict__ out, int D) {
    int row = blockIdx.x;
    const float* xr = x + (size_t)row * D;
    float s = 0.f, ss = 0.f;
    for (int c = threadIdx.x; c < D; c += 256) { float v = xr[c]; s += v; ss += v * v; }
    blockReduce2_256(s, ss);
    float mean = s / D;
    float var  = ss / D - mean * mean;
    float r = rsqrtf(var + LN_EPS);
    __half* orow = out + (size_t)row * D;
    for (int c = threadIdx.x; c < D; c += 256)
        orow[c] = __float2half((xr[c] - mean) * r * w[c] + b[c]);
}

// ---------------- sum split-K partials + LN2 -> fp16 ----------------
__global__ void reduce_ln2_kernel(const float* __restrict__ ln2_w,
                                  const float* __restrict__ ln2_b) {
    int row = blockIdx.x;
    __shared__ float v[DMODEL];
    float s = 0.f, ss = 0.f;
    for (int c = threadIdx.x; c < DMODEL; c += 256) {
        float t = 0.f;
        #pragma unroll
        for (int k = 0; k < KSPLIT; k++)
            t += g_part[(size_t)k * NTOK * DMODEL + (size_t)row * DMODEL + c];
        v[c] = t; s += t; ss += t * t;
    }
    blockReduce2_256(s, ss);
    float mean = s / DMODEL;
    float var  = ss / DMODEL - mean * mean;
    float r = rsqrtf(var + LN_EPS);
    __half* orow = g_mh + (size_t)row * DMODEL;
    for (int c = threadIdx.x; c < DMODEL; c += 256)
        orow[c] = __float2half((v[c] - mean) * r * ln2_w[c] + ln2_b[c]);
}

// ---------------- sum split-K partials + bias + residual -> out ----------------
__global__ void reduce_out_kernel(const float* __restrict__ bias,
                                  const float* __restrict__ resid,
                                  float* __restrict__ out) {
    int i = blockIdx.x * blockDim.x + threadIdx.x;    // float4 units
    if (i >= NTOK * DMODEL / 4) return;
    float4 acc = make_float4(0.f, 0.f, 0.f, 0.f);
    #pragma unroll
    for (int k = 0; k < KSPLIT; k++) {
        float4 p = ((const float4*)(g_part + (size_t)k * NTOK * DMODEL))[i];
        acc.x += p.x; acc.y += p.y; acc.z += p.z; acc.w += p.w;
    }
    int n4 = i % (DMODEL / 4);
    float4 bs = ((const float4*)bias)[n4];
    float4 rs = ((const float4*)resid)[i];
    acc.x += bs.x + rs.x; acc.y += bs.y + rs.y;
    acc.z += bs.z + rs.z; acc.w += bs.w + rs.w;
    ((float4*)out)[i] = acc;
}

// ---------------- fp16 tensor-core GEMM: C[M,N] = A[M,K] @ B[N,K]^T ----------------
// BM=128, BN=128, BK=64 (128B rows, SW128), 8 warps (4x2), warp tile 32x64.
// 3-stage cp.async pipeline (96 KB smem), 2 blocks/SM. 32 HMMAs between barriers.
#define NSTAGE 3
#define BKW    64
template<int BM, int BN, int WGM, int WGN>
__global__ __launch_bounds__(256, 2) void hgemm(
    const __half* __restrict__ A, const __half* __restrict__ B,
    int M, int N, int K,
    float* __restrict__ Cf, __half* __restrict__ Ch,
    const float* __restrict__ bias, const float* __restrict__ resid, int act)
{
    static_assert(WGM * WGN == 8, "8 warps");
    constexpr int WTM = BM / WGM;     // 32
    constexpr int WTN = BN / WGN;     // 64
    constexpr int MI  = WTM / 16;     // 2
    constexpr int NP  = WTN / 16;     // 4
    constexpr int NI  = WTN / 8;      // 8

    extern __shared__ __half smemh[];
    __half* As = smemh;                       // NSTAGE * BM * 64
    __half* Bs = smemh + NSTAGE * BM * BKW;   // NSTAGE * BN * 64

    int tid = threadIdx.x;
    int m0 = blockIdx.y * BM, n0 = blockIdx.x * BN;
    int lane = tid & 31, wid = tid >> 5;
    int wm = wid / WGN, wn = wid % WGN;

    int nsplit = gridDim.z;
    int kc = K / nsplit;
    int kbase = blockIdx.z * kc;
    bool is_split = nsplit > 1;
    if (is_split) Cf += (size_t)blockIdx.z * M * N;

    float c[MI][NI][4];
    #pragma unroll
    for (int mi = 0; mi < MI; mi++)
        #pragma unroll
        for (int ni = 0; ni < NI; ni++)
            #pragma unroll
            for (int r = 0; r < 4; r++) c[mi][ni][r] = 0.f;

    int KT = kc / BKW;

    auto load_stage = [&](int kt, int buf) {
        int k0 = kbase + kt * BKW;
        __half* Ab = As + buf * BM * BKW;
        __half* Bb = Bs + buf * BN * BKW;
        #pragma unroll
        for (int i = 0; i < BM / 32; i++) {        // BM*8 chunks / 256 threads
            int ch = tid + i * 256;
            int row = ch >> 3, cx = ch & 7;
            uint32_t da = sptr(&Ab[swz64(row, cx)]);
            const __half* sa = A + (size_t)(m0 + row) * K + k0 + cx * 8;
            asm volatile("cp.async.cg.shared.global [%0], [%1], 16;\n"
                         :: "r"(da), "l"(sa));
        }
        #pragma unroll
        for (int i = 0; i < BN / 32; i++) {
            int ch = tid + i * 256;
            int row = ch >> 3, cx = ch & 7;
            int gn = n0 + row;
            int valid = gn < N;
            uint32_t db = sptr(&Bb[swz64(row, cx)]);
            const __half* sb = B + (size_t)(valid ? gn : 0) * K + k0 + cx * 8;
            int sz = valid ? 16 : 0;
            asm volatile("cp.async.cg.shared.global [%0], [%1], 16, %2;\n"
                         :: "r"(db), "l"(sb), "r"(sz));
        }
    };

    #pragma unroll
    for (int s = 0; s < NSTAGE - 1; s++) {
        if (s < KT) load_stage(s, s);
        asm volatile("cp.async.commit_group;\n");
    }

    for (int kt = 0; kt < KT; kt++) {
        int buf = kt % NSTAGE;
        asm volatile("cp.async.wait_group %0;\n" :: "n"(NSTAGE - 2));
        __syncthreads();

        __half* Ab = As + buf * BM * BKW;
        __half* Bb = Bs + buf * BN * BKW;
        #pragma unroll
        for (int ks = 0; ks < 4; ks++) {           // 4 x K=16 within BK=64
            uint32_t a[MI][4];
            #pragma unroll
            for (int mi = 0; mi < MI; mi++) {
                int row = wm * WTM + mi * 16 + (lane & 15);
                int chunk = ks * 2 + (lane >> 4);
                ldsm4(a[mi], sptr(&Ab[swz64(row, chunk)]));
            }
            uint32_t b[NI][2];
            #pragma unroll
            for (int np = 0; np < NP; np++) {
                uint32_t t[4];
                int row = wn * WTN + np * 16 + (lane & 7) + ((lane >> 4) & 1) * 8;
                int chunk = ks * 2 + ((lane >> 3) & 1);
                ldsm4(t, sptr(&Bb[swz64(row, chunk)]));
                b[np * 2][0] = t[0]; b[np * 2][1] = t[1];
                b[np * 2 + 1][0] = t[2]; b[np * 2 + 1][1] = t[3];
            }
            #pragma unroll
            for (int mi = 0; mi < MI; mi++)
                #pragma unroll
                for (int ni = 0; ni < NI; ni++)
                    mma16816(c[mi][ni], a[mi], b[ni]);
        }

        int nx = kt + NSTAGE - 1;
        if (nx < KT) load_stage(nx, nx % NSTAGE);
        asm volatile("cp.async.commit_group;\n");
    }

    int gr = lane >> 2, tc = (lane & 3) * 2;
    #pragma unroll
    for (int mi = 0; mi < MI; mi++) {
        #pragma unroll
        for (int ni = 0; ni < NI; ni++) {
            int n = n0 + wn * WTN + ni * 8 + tc;
            if (n < N) {
                #pragma unroll
                for (int h = 0; h < 2; h++) {
                    int m = m0 + wm * WTM + mi * 16 + gr + h * 8;
                    float v0 = c[mi][ni][h * 2];
                    float v1 = c[mi][ni][h * 2 + 1];
                    if (!is_split) {
                        if (bias) { v0 += bias[n]; v1 += bias[n + 1]; }
                        if (act == 1) {
                            v0 = 0.5f * v0 * (1.f + erff(v0 * 0.70710678118654752f));
                            v1 = 0.5f * v1 * (1.f + erff(v1 * 0.70710678118654752f));
                        }
                        if (resid) {
                            v0 += resid[(size_t)m * N + n];
                            v1 += resid[(size_t)m * N + n + 1];
                        }
                        if (Ch) *(__half2*)&Ch[(size_t)m * N + n] = __floats2half2_rn(v0, v1);
                        if (Cf) { float2 o = make_float2(v0, v1); *(float2*)&Cf[(size_t)m * N + n] = o; }
                    } else {
                        float2 o = make_float2(v0, v1);
                        *(float2*)&Cf[(size_t)m * N + n] = o;
                    }
                }
            }
        }
    }
}

// ---------------- tiled conv (both dirs) + SiLU, with fused dt/dA ----------------
#define CT 16
#define CC 128
__global__ __launch_bounds__(256) void conv_silu_tile(const float* __restrict__ w,
                                                      const float* __restrict__ cb,
                                                      const float* __restrict__ dt_bias,
                                                      const float* __restrict__ A_log) {
    int cc = blockIdx.x;
    int tt = blockIdx.y;
    int b  = blockIdx.z;
    int c0 = cc * CC, t0 = tt * CT;
    __shared__ float tile[CT + 6][CC];
    __shared__ float wsh[4][CC];
    __shared__ float bsh[CC];

    if (cc == 0) {
        for (int i = threadIdx.x; i < CT * NHEADS; i += 256) {
            int r = i / NHEADS, h = i % NHEADS;
            int row = b * SEQ + t0 + r;
            float xv = g_zx[(size_t)row * DINPROJ + DINNER + CONVDIM + h] + dt_bias[h];
            float sp = (xv > 20.f) ? xv : log1pf(expf(xv));
            g_dt[(size_t)row * NHEADS + h] = sp;
            g_dA[(size_t)row * NHEADS + h] = expf(-expf(A_log[h]) * sp);
        }
    }

    for (int i = threadIdx.x; i < CC * 4; i += 256) {
        int c = i & (CC - 1), k = i >> 7;
        wsh[k][c] = w[(c0 + c) * 4 + k];
    }
    for (int i = threadIdx.x; i < CC; i += 256) bsh[i] = cb[c0 + i];

    const float* base = g_zx + (size_t)(b * SEQ) * DINPROJ + DINNER + c0;
    for (int i = threadIdx.x; i < (CT + 6) * CC; i += 256) {
        int r = i / CC, c = i % CC;
        int t = t0 - 3 + r;
        tile[r][c] = (t >= 0 && t < SEQ) ? base[(size_t)t * DINPROJ + c] : 0.f;
    }
    __syncthreads();

    for (int i = threadIdx.x; i < CT * CC; i += 256) {
        int r = i / CC, c = i % CC;
        int row = b * SEQ + t0 + r;
        float sf = bsh[c], sb2 = bsh[c];
        #pragma unroll
        for (int k = 0; k < 4; k++) {
            sf  = fmaf(wsh[k][c], tile[r + k][c],     sf);
            sb2 = fmaf(wsh[k][c], tile[r + 6 - k][c], sb2);
        }
        g_xBC[(size_t)row * CONVDIM + c0 + c]          = sf  / (1.f + expf(-sf));
        g_xBC[(size_t)(NTOK + row) * CONVDIM + c0 + c] = sb2 / (1.f + expf(-sb2));
    }
}

// ---------------- scan pass A: per-chunk local scan (h_init = 0) ----------------
__global__ __launch_bounds__(256) void scanA_kernel(const float* __restrict__ D_param) {
    int h = blockIdx.x, b = blockIdx.y;
    int dir = blockIdx.z / NC, chunk = blockIdx.z % NC;
    int idx = (dir * BSZ + b) * NHEADS + h;
    const float* xbc  = g_xBC + (size_t)(dir * NTOK + b * SEQ) * CONVDIM;
    float*       yout = g_y   + (size_t)(dir * NTOK + b * SEQ) * DINNER;
    int tid = threadIdx.x;
    int p = tid >> 2, q = tid & 3, nbase = q * 16;
    int s0 = chunk * LC;

    __shared__ float sdt[LC], sdA[LC];
    __shared__ __align__(16) float sbuf[2][192];

    for (int i = tid; i < LC; i += 256) {
        int t = dir ? (SEQ - 1 - (s0 + i)) : (s0 + i);
        sdt[i] = g_dt[(size_t)(b * SEQ + t) * NHEADS + h];
        sdA[i] = g_dA[(size_t)(b * SEQ + t) * NHEADS + h];
    }

    ull hr2[8];
    #pragma unroll
    for (int i = 0; i < 8; i++) hr2[i] = 0ull;
    float Dp = D_param[h];
    float cum = 1.f;

    auto gload = [&](int s) -> float {
        int t = dir ? (SEQ - 1 - s) : s;
        const float* r = xbc + (size_t)t * CONVDIM;
        if (tid < 64)  return r[h * 64 + tid];
        if (tid < 192) return r[DINNER + (tid - 64)];
        return 0.f;
    };

    float staged = gload(s0);

    for (int sl = 0; sl < LC; sl++) {
        int s = s0 + sl;
        int t = dir ? (SEQ - 1 - s) : s;
        int buf = sl & 1;
        if (tid < 192) sbuf[buf][tid] = staged;
        __syncthreads();
        if (sl + 1 < LC) staged = gload(s + 1);

        float xp  = sbuf[buf][p];
        float dtv = sdt[sl];
        float dAv = sdA[sl];
        float bx  = dtv * xp;
        cum *= dAv;

        ull B2[8], C2[8];
        const longlong2* Bp = (const longlong2*)&sbuf[buf][64 + nbase];
        const longlong2* Cp = (const longlong2*)&sbuf[buf][128 + nbase];
        #pragma unroll
        for (int i = 0; i < 4; i++) {
            longlong2 v = Bp[i]; B2[2 * i] = (ull)v.x; B2[2 * i + 1] = (ull)v.y;
            longlong2 u = Cp[i]; C2[2 * i] = (ull)u.x; C2[2 * i + 1] = (ull)u.y;
        }
        ull bx2 = pack2(bx, bx);
        ull dA2 = pack2(dAv, dAv);
        ull acca = 0ull, accb = 0ull;
        #pragma unroll
        for (int i = 0; i < 8; i += 2) {
            hr2[i]     = fma2(dA2, hr2[i],     mul2(bx2, B2[i]));
            hr2[i + 1] = fma2(dA2, hr2[i + 1], mul2(bx2, B2[i + 1]));
            acca = fma2(hr2[i],     C2[i],     acca);
            accb = fma2(hr2[i + 1], C2[i + 1], accb);
        }
        ull accp = add2(acca, accb);
        float a0, a1; unpack2(accp, a0, a1);
        float acc = a0 + a1;
        acc += __shfl_xor_sync(0xffffffffu, acc, 1);
        acc += __shfl_xor_sync(0xffffffffu, acc, 2);
        if (q == 0) yout[(size_t)t * DINNER + h * 64 + p] = fmaf(Dp, xp, acc);
        if (tid == 0) g_cum[(size_t)idx * SEQ + s] = cum;
    }

    float* st = g_state + ((size_t)idx * NC + chunk) * 4096 + tid * 16;
    #pragma unroll
    for (int i = 0; i < 8; i++) {
        float x0, x1; unpack2(hr2[i], x0, x1);
        st[2 * i] = x0; st[2 * i + 1] = x1;
    }
}

// ---------------- scan pass C: inline combine + correction ----------------
__global__ __launch_bounds__(256) void scanC_kernel() {
    int h = blockIdx.x, b = blockIdx.y;
    int dir = blockIdx.z / (NC - 1), chunk = blockIdx.z % (NC - 1) + 1;
    int idx = (dir * BSZ + b) * NHEADS + h;
    const float* xbc  = g_xBC + (size_t)(dir * NTOK + b * SEQ) * CONVDIM;
    float*       yout = g_y   + (size_t)(dir * NTOK + b * SEQ) * DINNER;
    int tid = threadIdx.x;
    int p = tid >> 2, q = tid & 3, nbase = q * 16;
    int s0 = chunk * LC;

    __shared__ float scum[LC];
    __shared__ __align__(16) float sC[2][64];

    for (int i = tid; i < LC; i += 256)
        scum[i] = g_cum[(size_t)idx * SEQ + s0 + i];

    float hin[16];
    #pragma unroll
    for (int i = 0; i < 16; i++) hin[i] = 0.f;
    for (int j = 0; j < chunk; j++) {
        float P = g_cum[(size_t)idx * SEQ + j * LC + LC - 1];
        const float4* L = (const float4*)(g_state + ((size_t)idx * NC + j) * 4096 + tid * 16);
        #pragma unroll
        for (int i = 0; i < 4; i++) {
            float4 l = L[i];
            hin[4 * i]     = fmaf(P, hin[4 * i],     l.x);
            hin[4 * i + 1] = fmaf(P, hin[4 * i + 1], l.y);
            hin[4 * i + 2] = fmaf(P, hin[4 * i + 2], l.z);
            hin[4 * i + 3] = fmaf(P, hin[4 * i + 3], l.w);
        }
    }

    auto gloadC = [&](int s) -> float {
        int t = dir ? (SEQ - 1 - s) : s;
        if (tid < 64) return xbc[(size_t)t * CONVDIM + DINNER + DSTATE + tid];
        return 0.f;
    };

    float staged = gloadC(s0);

    for (int sl = 0; sl < LC; sl++) {
        int s = s0 + sl;
        int t = dir ? (SEQ - 1 - s) : s;
        int buf = sl & 1;
        if (tid < 64) sC[buf][tid] = staged;
        __syncthreads();
        if (sl + 1 < LC) staged = gloadC(s + 1);

        const float* Cv = &sC[buf][nbase];
        float acc = 0.f;
        #pragma unroll
        for (int i = 0; i < 16; i++) acc = fmaf(Cv[i], hin[i], acc);
        acc += __shfl_xor_sync(0xffffffffu, acc, 1);
        acc += __shfl_xor_sync(0xffffffffu, acc, 2);
        if (q == 0) {
            float* yp = &yout[(size_t)t * DINNER + h * 64 + p];
            *yp = fmaf(scum[sl], acc, *yp);
        }
    }
}

// ---------------- gate with SiLU(z), per-direction RMSNorm, sum dirs (fp16 out) ----------------
__global__ void gate_rms_kernel(const float* __restrict__ norm_w) {
    int row = blockIdx.x;
    __shared__ float gf[DINNER];
    __shared__ float gb[DINNER];
    const float* zr = g_zx + (size_t)row * DINPROJ;
    const float* yf = g_y  + (size_t)row * DINNER;
    const float* yb = g_y  + (size_t)(NTOK + row) * DINNER;
    float ssf = 0.f, ssb = 0.f;
    for (int c = threadIdx.x; c < DINNER; c += 256) {
        float zc = zr[c];
        float sz = zc / (1.f + expf(-zc));
        float a  = yf[c] * sz;
        float bb = yb[c] * sz;
        gf[c] = a; gb[c] = bb;
        ssf += a * a; ssb += bb * bb;
    }
    blockReduce2_256(ssf, ssb);
    float rf = rsqrtf(ssf / DINNER + LN_EPS);
    float rb = rsqrtf(ssb / DINNER + LN_EPS);
    __half* orow = g_gsumh + (size_t)row * DINNER;
    for (int c = threadIdx.x; c < DINNER; c += 256)
        orow[c] = __float2half((gf[c] * rf + gb[c] * rb) * norm_w[c]);
}

// ---------------- launch ----------------
extern "C" void kernel_launch(void* const* d_in, const int* in_sizes, int n_in,
                              void* d_out, int out_size) {
    const float* x         = (const float*)d_in[0];
    const float* in_proj_w = (const float*)d_in[1];
    const float* conv_w    = (const float*)d_in[2];
    const float* conv_b    = (const float*)d_in[3];
    const float* dt_bias   = (const float*)d_in[4];
    const float* A_log     = (const float*)d_in[5];
    const float* D_param   = (const float*)d_in[6];
    const float* norm_w    = (const float*)d_in[7];
    const float* out_proj_w= (const float*)d_in[8];
    const float* ln1_w     = (const float*)d_in[9];
    const float* ln1_b     = (const float*)d_in[10];
    const float* ln2_w     = (const float*)d_in[11];
    const float* ln2_b     = (const float*)d_in[12];
    const float* ff_w1     = (const float*)d_in[13];
    const float* ff_b1     = (const float*)d_in[14];
    const float* ff_w2     = (const float*)d_in[15];
    const float* ff_b2     = (const float*)d_in[16];
    float* out = (float*)d_out;

    void *p_zx, *p_xnh, *p_gsumh, *p_mh, *p_ff1h;
    void *p_wi, *p_wo, *p_w1, *p_w2, *p_part;
    cudaGetSymbolAddress(&p_zx,    g_zx);
    cudaGetSymbolAddress(&p_part,  g_part);
    cudaGetSymbolAddress(&p_xnh,   g_xnh);
    cudaGetSymbolAddress(&p_gsumh, g_gsumh);
    cudaGetSymbolAddress(&p_mh,    g_mh);
    cudaGetSymbolAddress(&p_ff1h,  g_ff1h);
    cudaGetSymbolAddress(&p_wi,    g_w_inproj_h);
    cudaGetSymbolAddress(&p_wo,    g_w_outproj_h);
    cudaGetSymbolAddress(&p_w1,    g_w_ff1_h);
    cudaGetSymbolAddress(&p_w2,    g_w_ff2_h);

    const int smemG = NSTAGE * (128 + 128) * BKW * sizeof(__half);   // 96 KB
    cudaFuncSetAttribute((const void*)hgemm<128,128,4,2>,
                         cudaFuncAttributeMaxDynamicSharedMemorySize, smemG);

    // 1) LN1 -> fp16 xn
    ln_kernel<<<NTOK, 256>>>(x, ln1_w, ln1_b, (__half*)p_xnh, DMODEL);

    // 2) all weight conversions in one launch
    {
        int n0 = DINPROJ * DMODEL / 8;
        int n1 = DMODEL * DINNER / 8;
        int n2 = DFF * DMODEL / 8;
        int n3 = DMODEL * DFF / 8;
        int tot = n0 + n1 + n2 + n3;
        f2h_all_kernel<<<(tot + 255) / 256, 256>>>(
            in_proj_w, (__half*)p_wi, n0,
            out_proj_w, (__half*)p_wo, n1,
            ff_w1, (__half*)p_w1, n2,
            ff_w2, (__half*)p_w2, n3);
    }

    // 3) in_proj GEMM: 26x8 = 208 blocks
    hgemm<128,128,4,2><<<dim3((DINPROJ + 127) / 128, NTOK / 128), 256, smemG>>>(
        (const __half*)p_xnh, (const __half*)p_wi,
        NTOK, DINPROJ, DMODEL, (float*)p_zx, nullptr, nullptr, nullptr, 0);

    // 4) conv + SiLU (both directions) with fused dt/dA
    conv_silu_tile<<<dim3(CONVDIM / CC, SEQ / CT, BSZ), 256>>>(conv_w, conv_b, dt_bias, A_log);

    // 5) chunked selective scan
    scanA_kernel<<<dim3(NHEADS, BSZ, 2 * NC), 256>>>(D_param);
    scanC_kernel<<<dim3(NHEADS, BSZ, 2 * (NC - 1)), 256>>>();

    // 6) gate + RMSNorm + direction-sum -> fp16
    gate_rms_kernel<<<NTOK, 256>>>(norm_w);

    // 7) out_proj GEMM split-K x6 -> partials: 6x8x6 = 288 blocks
    hgemm<128,128,4,2><<<dim3(DMODEL / 128, NTOK / 128, KSPLIT), 256, smemG>>>(
        (const __half*)p_gsumh, (const __half*)p_wo,
        NTOK, DMODEL, DINNER, (float*)p_part, nullptr, nullptr, nullptr, 0);

    // 8) reduce partials + LN2 -> fp16 m
    reduce_ln2_kernel<<<NTOK, 256>>>(ln2_w, ln2_b);

    // 9) FF1 + bias + GELU -> fp16: 24x8 = 192 blocks
    hgemm<128,128,4,2><<<dim3(DFF / 128, NTOK / 128), 256, smemG>>>(
        (const __half*)p_mh, (const __half*)p_w1,
        NTOK, DFF, DMODEL, nullptr, (__half*)p_ff1h, ff_b1, nullptr, 1);

    // 10) FF2 split-K x6 -> partials: 288 blocks
    hgemm<128,128,4,2><<<dim3(DMODEL / 128, NTOK / 128, KSPLIT), 256, smemG>>>(
        (const __half*)p_ff1h, (const __half*)p_w2,
        NTOK, DMODEL, DFF, (float*)p_part, nullptr, nullptr, nullptr, 0);

    // 11) reduce partials + bias + residual -> out
    reduce_out_kernel<<<(NTOK * DMODEL / 4 + 255) / 256, 256>>>(ff_b2, x, out);
}

// round 17
// speedup vs baseline: 1.5793x; 1.0015x over previous
#include <cuda_runtime.h>
#include <cuda_fp16.h>
#include <math.h>
#include <stdint.h>

#define BSZ     2
#define SEQ     512
#define DMODEL  768
#define DINNER  1536
#define DSTATE  64
#define NHEADS  24
#define HEADDIM 64
#define CONVDIM 1664            // DINNER + 2*DSTATE
#define DINPROJ 3224            // 2*DINNER + 2*DSTATE + NHEADS
#define NTOK    (BSZ*SEQ)       // 1024
#define DFF     3072
#define LN_EPS  1e-5f
#define LC      64              // scan chunk length
#define NC      (SEQ/LC)        // 8 chunks
#define NSCAN   (2*BSZ*NHEADS)  // 96
#define KSPLIT  6

typedef unsigned long long ull;

// ---------------- scratch (static device globals; no allocation) ----------------
__device__ float  g_zx  [NTOK*DINPROJ];
__device__ float  g_xBC [2*NTOK*CONVDIM];
__device__ float  g_dt  [NTOK*NHEADS];
__device__ float  g_dA  [NTOK*NHEADS];
__device__ float  g_y   [2*NTOK*DINNER];
__device__ float  g_part[KSPLIT*NTOK*DMODEL];  // split-K partials
__device__ float  g_state[NSCAN*NC*4096];
__device__ float  g_cum  [NSCAN*SEQ];
// fp16 activations / weights
__device__ __half g_xnh   [NTOK*DMODEL];
__device__ __half g_gsumh [NTOK*DINNER];
__device__ __half g_mh    [NTOK*DMODEL];
__device__ __half g_ff1h  [NTOK*DFF];
__device__ __half g_w_inproj_h [DINPROJ*DMODEL];
__device__ __half g_w_outproj_h[DMODEL*DINNER];
__device__ __half g_w_ff1_h    [DFF*DMODEL];
__device__ __half g_w_ff2_h    [DMODEL*DFF];

// ---------------- helpers ----------------
__device__ __forceinline__ uint32_t sptr(const void* p) {
    return (uint32_t)__cvta_generic_to_shared(p);
}
__device__ __forceinline__ void ldsm4(uint32_t* r, uint32_t addr) {
    asm volatile("ldmatrix.sync.aligned.m8n8.x4.shared.b16 {%0,%1,%2,%3}, [%4];"
                 : "=r"(r[0]), "=r"(r[1]), "=r"(r[2]), "=r"(r[3]) : "r"(addr));
}
__device__ __forceinline__ void mma16816(float* c, const uint32_t* a, const uint32_t* b) {
    asm volatile("mma.sync.aligned.m16n8k16.row.col.f32.f16.f16.f32 "
                 "{%0,%1,%2,%3}, {%4,%5,%6,%7}, {%8,%9}, {%0,%1,%2,%3};"
                 : "+f"(c[0]), "+f"(c[1]), "+f"(c[2]), "+f"(c[3])
                 : "r"(a[0]), "r"(a[1]), "r"(a[2]), "r"(a[3]), "r"(b[0]), "r"(b[1]));
}
// packed fp32x2 math (FFMA2 — only reachable via PTX)
__device__ __forceinline__ ull pack2(float x, float y) {
    ull r; asm("mov.b64 %0,{%1,%2};" : "=l"(r) : "f"(x), "f"(y)); return r;
}
__device__ __forceinline__ void unpack2(ull v, float& x, float& y) {
    asm("mov.b64 {%0,%1},%2;" : "=f"(x), "=f"(y) : "l"(v));
}
__device__ __forceinline__ ull fma2(ull a, ull b, ull c) {
    ull d; asm("fma.rn.f32x2 %0,%1,%2,%3;" : "=l"(d) : "l"(a), "l"(b), "l"(c)); return d;
}
__device__ __forceinline__ ull mul2(ull a, ull b) {
    ull d; asm("mul.rn.f32x2 %0,%1,%2;" : "=l"(d) : "l"(a), "l"(b)); return d;
}
__device__ __forceinline__ ull add2(ull a, ull b) {
    ull d; asm("add.rn.f32x2 %0,%1,%2;" : "=l"(d) : "l"(a), "l"(b)); return d;
}
// SW128 swizzle for 128-byte (64-half) rows: 16B chunk index XORed with row%8.
__device__ __forceinline__ int swz64(int row, int chunk) {
    return row * 64 + ((chunk ^ (row & 7)) << 3);
}

// ---------------- fused fp32 -> fp16 convert, 16 elems/thread (MLP=4) ----------------
__global__ void f2h_all_kernel(const float* __restrict__ w0, __half* __restrict__ o0, int n0,
                               const float* __restrict__ w1, __half* __restrict__ o1, int n1,
                               const float* __restrict__ w2, __half* __restrict__ o2, int n2,
                               const float* __restrict__ w3, __half* __restrict__ o3, int n3) {
    int i = blockIdx.x * blockDim.x + threadIdx.x;   // index in 16-elem units
    const float* in; __half* out; int local;
    if (i < n0)                { in = w0; out = o0; local = i; }
    else if (i < n0 + n1)      { in = w1; out = o1; local = i - n0; }
    else if (i < n0 + n1 + n2) { in = w2; out = o2; local = i - n0 - n1; }
    else if (i < n0 + n1 + n2 + n3) { in = w3; out = o3; local = i - n0 - n1 - n2; }
    else return;
    const float4* src = (const float4*)in + 4 * (size_t)local;
    float4 a = src[0];
    float4 b = src[1];
    float4 c = src[2];
    float4 d = src[3];
    __half2 h[8];
    h[0] = __floats2half2_rn(a.x, a.y); h[1] = __floats2half2_rn(a.z, a.w);
    h[2] = __floats2half2_rn(b.x, b.y); h[3] = __floats2half2_rn(b.z, b.w);
    h[4] = __floats2half2_rn(c.x, c.y); h[5] = __floats2half2_rn(c.z, c.w);
    h[6] = __floats2half2_rn(d.x, d.y); h[7] = __floats2half2_rn(d.z, d.w);
    uint4* dst = (uint4*)&out[16 * (size_t)local];
    dst[0] = *(uint4*)&h[0];
    dst[1] = *(uint4*)&h[4];
}

// ---------------- block reduce (256 threads, two values) ----------------
__device__ __forceinline__ void blockReduce2_256(float& a, float& b) {
    __shared__ float sa[8], sb[8];
    #pragma unroll
    for (int o = 16; o > 0; o >>= 1) {
        a += __shfl_xor_sync(0xffffffffu, a, o);
        b += __shfl_xor_sync(0xffffffffu, b, o);
    }
    int w = threadIdx.x >> 5, l = threadIdx.x & 31;
    if (l == 0) { sa[w] = a; sb[w] = b; }
    __syncthreads();
    if (w == 0) {
        a = (l < 8) ? sa[l] : 0.f;
        b = (l < 8) ? sb[l] : 0.f;
        #pragma unroll
        for (int o = 4; o > 0; o >>= 1) {
            a += __shfl_xor_sync(0xffffffffu, a, o);
            b += __shfl_xor_sync(0xffffffffu, b, o);
        }
        if (l == 0) { sa[0] = a; sb[0] = b; }
    }
    __syncthreads();
    a = sa[0]; b = sb[0];
}

// ---------------- layernorm (fp32 in, fp16 out) ----------------
__global__ void ln_kernel(const float* __restrict__ x, const float* __restrict__ w,
                          const float* __restrict__ b, __half* __restrict__ out, int D) {
    int row = blockIdx.x;
    const float* xr = x + (size_t)row * D;
    float s = 0.f, ss = 0.f;
    for (int c = threadIdx.x; c < D; c += 256) { float v = xr[c]; s += v; ss += v * v; }
    blockReduce2_256(s, ss);
    float mean = s / D;
    float var  = ss / D - mean * mean;
    float r = rsqrtf(var + LN_EPS);
    __half* orow = out + (size_t)row * D;
    for (int c = threadIdx.x; c < D; c += 256)
        orow[c] = __float2half((xr[c] - mean) * r * w[c] + b[c]);
}

// ---------------- sum split-K partials + LN2 -> fp16 ----------------
__global__ void reduce_ln2_kernel(const float* __restrict__ ln2_w,
                                  const float* __restrict__ ln2_b) {
    int row = blockIdx.x;
    __shared__ float v[DMODEL];
    float s = 0.f, ss = 0.f;
    for (int c = threadIdx.x; c < DMODEL; c += 256) {
        float t = 0.f;
        #pragma unroll
        for (int k = 0; k < KSPLIT; k++)
            t += g_part[(size_t)k * NTOK * DMODEL + (size_t)row * DMODEL + c];
        v[c] = t; s += t; ss += t * t;
    }
    blockReduce2_256(s, ss);
    float mean = s / DMODEL;
    float var  = ss / DMODEL - mean * mean;
    float r = rsqrtf(var + LN_EPS);
    __half* orow = g_mh + (size_t)row * DMODEL;
    for (int c = threadIdx.x; c < DMODEL; c += 256)
        orow[c] = __float2half((v[c] - mean) * r * ln2_w[c] + ln2_b[c]);
}

// ---------------- sum split-K partials + bias + residual -> out ----------------
__global__ void reduce_out_kernel(const float* __restrict__ bias,
                                  const float* __restrict__ resid,
                                  float* __restrict__ out) {
    int i = blockIdx.x * blockDim.x + threadIdx.x;    // float4 units
    if (i >= NTOK * DMODEL / 4) return;
    float4 acc = make_float4(0.f, 0.f, 0.f, 0.f);
    #pragma unroll
    for (int k = 0; k < KSPLIT; k++) {
        float4 p = ((const float4*)(g_part + (size_t)k * NTOK * DMODEL))[i];
        acc.x += p.x; acc.y += p.y; acc.z += p.z; acc.w += p.w;
    }
    int n4 = i % (DMODEL / 4);
    float4 bs = ((const float4*)bias)[n4];
    float4 rs = ((const float4*)resid)[i];
    acc.x += bs.x + rs.x; acc.y += bs.y + rs.y;
    acc.z += bs.z + rs.z; acc.w += bs.w + rs.w;
    ((float4*)out)[i] = acc;
}

// ---------------- fp16 tensor-core GEMM: C[M,N] = A[M,K] @ B[N,K]^T ----------------
// BM=128, BN=128, BK=64 (128B rows, SW128), 8 warps (4x2), warp tile 32x64.
// 3-stage cp.async pipeline (96 KB smem), 2 blocks/SM. 32 HMMAs between barriers.
#define NSTAGE 3
#define BKW    64
template<int BM, int BN, int WGM, int WGN>
__global__ __launch_bounds__(256, 2) void hgemm(
    const __half* __restrict__ A, const __half* __restrict__ B,
    int M, int N, int K,
    float* __restrict__ Cf, __half* __restrict__ Ch,
    const float* __restrict__ bias, const float* __restrict__ resid, int act)
{
    static_assert(WGM * WGN == 8, "8 warps");
    constexpr int WTM = BM / WGM;     // 32
    constexpr int WTN = BN / WGN;     // 64
    constexpr int MI  = WTM / 16;     // 2
    constexpr int NP  = WTN / 16;     // 4
    constexpr int NI  = WTN / 8;      // 8

    extern __shared__ __half smemh[];
    __half* As = smemh;                       // NSTAGE * BM * 64
    __half* Bs = smemh + NSTAGE * BM * BKW;   // NSTAGE * BN * 64

    int tid = threadIdx.x;
    int m0 = blockIdx.y * BM, n0 = blockIdx.x * BN;
    int lane = tid & 31, wid = tid >> 5;
    int wm = wid / WGN, wn = wid % WGN;

    int nsplit = gridDim.z;
    int kc = K / nsplit;
    int kbase = blockIdx.z * kc;
    bool is_split = nsplit > 1;
    if (is_split) Cf += (size_t)blockIdx.z * M * N;

    float c[MI][NI][4];
    #pragma unroll
    for (int mi = 0; mi < MI; mi++)
        #pragma unroll
        for (int ni = 0; ni < NI; ni++)
            #pragma unroll
            for (int r = 0; r < 4; r++) c[mi][ni][r] = 0.f;

    int KT = kc / BKW;

    auto load_stage = [&](int kt, int buf) {
        int k0 = kbase + kt * BKW;
        __half* Ab = As + buf * BM * BKW;
        __half* Bb = Bs + buf * BN * BKW;
        #pragma unroll
        for (int i = 0; i < BM / 32; i++) {        // BM*8 chunks / 256 threads
            int ch = tid + i * 256;
            int row = ch >> 3, cx = ch & 7;
            uint32_t da = sptr(&Ab[swz64(row, cx)]);
            const __half* sa = A + (size_t)(m0 + row) * K + k0 + cx * 8;
            asm volatile("cp.async.cg.shared.global [%0], [%1], 16;\n"
                         :: "r"(da), "l"(sa));
        }
        #pragma unroll
        for (int i = 0; i < BN / 32; i++) {
            int ch = tid + i * 256;
            int row = ch >> 3, cx = ch & 7;
            int gn = n0 + row;
            int valid = gn < N;
            uint32_t db = sptr(&Bb[swz64(row, cx)]);
            const __half* sb = B + (size_t)(valid ? gn : 0) * K + k0 + cx * 8;
            int sz = valid ? 16 : 0;
            asm volatile("cp.async.cg.shared.global [%0], [%1], 16, %2;\n"
                         :: "r"(db), "l"(sb), "r"(sz));
        }
    };

    #pragma unroll
    for (int s = 0; s < NSTAGE - 1; s++) {
        if (s < KT) load_stage(s, s);
        asm volatile("cp.async.commit_group;\n");
    }

    for (int kt = 0; kt < KT; kt++) {
        int buf = kt % NSTAGE;
        asm volatile("cp.async.wait_group %0;\n" :: "n"(NSTAGE - 2));
        __syncthreads();

        __half* Ab = As + buf * BM * BKW;
        __half* Bb = Bs + buf * BN * BKW;
        #pragma unroll
        for (int ks = 0; ks < 4; ks++) {           // 4 x K=16 within BK=64
            uint32_t a[MI][4];
            #pragma unroll
            for (int mi = 0; mi < MI; mi++) {
                int row = wm * WTM + mi * 16 + (lane & 15);
                int chunk = ks * 2 + (lane >> 4);
                ldsm4(a[mi], sptr(&Ab[swz64(row, chunk)]));
            }
            uint32_t b[NI][2];
            #pragma unroll
            for (int np = 0; np < NP; np++) {
                uint32_t t[4];
                int row = wn * WTN + np * 16 + (lane & 7) + ((lane >> 4) & 1) * 8;
                int chunk = ks * 2 + ((lane >> 3) & 1);
                ldsm4(t, sptr(&Bb[swz64(row, chunk)]));
                b[np * 2][0] = t[0]; b[np * 2][1] = t[1];
                b[np * 2 + 1][0] = t[2]; b[np * 2 + 1][1] = t[3];
            }
            #pragma unroll
            for (int mi = 0; mi < MI; mi++)
                #pragma unroll
                for (int ni = 0; ni < NI; ni++)
                    mma16816(c[mi][ni], a[mi], b[ni]);
        }

        int nx = kt + NSTAGE - 1;
        if (nx < KT) load_stage(nx, nx % NSTAGE);
        asm volatile("cp.async.commit_group;\n");
    }

    int gr = lane >> 2, tc = (lane & 3) * 2;
    #pragma unroll
    for (int mi = 0; mi < MI; mi++) {
        #pragma unroll
        for (int ni = 0; ni < NI; ni++) {
            int n = n0 + wn * WTN + ni * 8 + tc;
            if (n < N) {
                #pragma unroll
                for (int h = 0; h < 2; h++) {
                    int m = m0 + wm * WTM + mi * 16 + gr + h * 8;
                    float v0 = c[mi][ni][h * 2];
                    float v1 = c[mi][ni][h * 2 + 1];
                    if (!is_split) {
                        if (bias) { v0 += bias[n]; v1 += bias[n + 1]; }
                        if (act == 1) {
                            v0 = 0.5f * v0 * (1.f + erff(v0 * 0.70710678118654752f));
                            v1 = 0.5f * v1 * (1.f + erff(v1 * 0.70710678118654752f));
                        }
                        if (resid) {
                            v0 += resid[(size_t)m * N + n];
                            v1 += resid[(size_t)m * N + n + 1];
                        }
                        if (Ch) *(__half2*)&Ch[(size_t)m * N + n] = __floats2half2_rn(v0, v1);
                        if (Cf) { float2 o = make_float2(v0, v1); *(float2*)&Cf[(size_t)m * N + n] = o; }
                    } else {
                        float2 o = make_float2(v0, v1);
                        *(float2*)&Cf[(size_t)m * N + n] = o;
                    }
                }
            }
        }
    }
}

// ---------------- tiled conv (both dirs) + SiLU, with fused dt/dA ----------------
#define CT 16
#define CC 128
__global__ __launch_bounds__(256) void conv_silu_tile(const float* __restrict__ w,
                                                      const float* __restrict__ cb,
                                                      const float* __restrict__ dt_bias,
                                                      const float* __restrict__ A_log) {
    int cc = blockIdx.x;
    int tt = blockIdx.y;
    int b  = blockIdx.z;
    int c0 = cc * CC, t0 = tt * CT;
    __shared__ float tile[CT + 6][CC];
    __shared__ float wsh[4][CC];
    __shared__ float bsh[CC];

    if (cc == 0) {
        for (int i = threadIdx.x; i < CT * NHEADS; i += 256) {
            int r = i / NHEADS, h = i % NHEADS;
            int row = b * SEQ + t0 + r;
            float xv = g_zx[(size_t)row * DINPROJ + DINNER + CONVDIM + h] + dt_bias[h];
            float sp = (xv > 20.f) ? xv : log1pf(expf(xv));
            g_dt[(size_t)row * NHEADS + h] = sp;
            g_dA[(size_t)row * NHEADS + h] = expf(-expf(A_log[h]) * sp);
        }
    }

    for (int i = threadIdx.x; i < CC * 4; i += 256) {
        int c = i & (CC - 1), k = i >> 7;
        wsh[k][c] = w[(c0 + c) * 4 + k];
    }
    for (int i = threadIdx.x; i < CC; i += 256) bsh[i] = cb[c0 + i];

    const float* base = g_zx + (size_t)(b * SEQ) * DINPROJ + DINNER + c0;
    for (int i = threadIdx.x; i < (CT + 6) * CC; i += 256) {
        int r = i / CC, c = i % CC;
        int t = t0 - 3 + r;
        tile[r][c] = (t >= 0 && t < SEQ) ? base[(size_t)t * DINPROJ + c] : 0.f;
    }
    __syncthreads();

    for (int i = threadIdx.x; i < CT * CC; i += 256) {
        int r = i / CC, c = i % CC;
        int row = b * SEQ + t0 + r;
        float sf = bsh[c], sb2 = bsh[c];
        #pragma unroll
        for (int k = 0; k < 4; k++) {
            sf  = fmaf(wsh[k][c], tile[r + k][c],     sf);
            sb2 = fmaf(wsh[k][c], tile[r + 6 - k][c], sb2);
        }
        g_xBC[(size_t)row * CONVDIM + c0 + c]          = sf  / (1.f + expf(-sf));
        g_xBC[(size_t)(NTOK + row) * CONVDIM + c0 + c] = sb2 / (1.f + expf(-sb2));
    }
}

// ---------------- scan pass A: per-chunk local scan (h_init = 0) ----------------
__global__ __launch_bounds__(256) void scanA_kernel(const float* __restrict__ D_param) {
    int h = blockIdx.x, b = blockIdx.y;
    int dir = blockIdx.z / NC, chunk = blockIdx.z % NC;
    int idx = (dir * BSZ + b) * NHEADS + h;
    const float* xbc  = g_xBC + (size_t)(dir * NTOK + b * SEQ) * CONVDIM;
    float*       yout = g_y   + (size_t)(dir * NTOK + b * SEQ) * DINNER;
    int tid = threadIdx.x;
    int p = tid >> 2, q = tid & 3, nbase = q * 16;
    int s0 = chunk * LC;

    __shared__ float sdt[LC], sdA[LC];
    __shared__ __align__(16) float sbuf[2][192];

    for (int i = tid; i < LC; i += 256) {
        int t = dir ? (SEQ - 1 - (s0 + i)) : (s0 + i);
        sdt[i] = g_dt[(size_t)(b * SEQ + t) * NHEADS + h];
        sdA[i] = g_dA[(size_t)(b * SEQ + t) * NHEADS + h];
    }

    ull hr2[8];
    #pragma unroll
    for (int i = 0; i < 8; i++) hr2[i] = 0ull;
    float Dp = D_param[h];
    float cum = 1.f;

    auto gload = [&](int s) -> float {
        int t = dir ? (SEQ - 1 - s) : s;
        const float* r = xbc + (size_t)t * CONVDIM;
        if (tid < 64)  return r[h * 64 + tid];
        if (tid < 192) return r[DINNER + (tid - 64)];
        return 0.f;
    };

    float staged = gload(s0);

    for (int sl = 0; sl < LC; sl++) {
        int s = s0 + sl;
        int t = dir ? (SEQ - 1 - s) : s;
        int buf = sl & 1;
        if (tid < 192) sbuf[buf][tid] = staged;
        __syncthreads();
        if (sl + 1 < LC) staged = gload(s + 1);

        float xp  = sbuf[buf][p];
        float dtv = sdt[sl];
        float dAv = sdA[sl];
        float bx  = dtv * xp;
        cum *= dAv;

        ull B2[8], C2[8];
        const longlong2* Bp = (const longlong2*)&sbuf[buf][64 + nbase];
        const longlong2* Cp = (const longlong2*)&sbuf[buf][128 + nbase];
        #pragma unroll
        for (int i = 0; i < 4; i++) {
            longlong2 v = Bp[i]; B2[2 * i] = (ull)v.x; B2[2 * i + 1] = (ull)v.y;
            longlong2 u = Cp[i]; C2[2 * i] = (ull)u.x; C2[2 * i + 1] = (ull)u.y;
        }
        ull bx2 = pack2(bx, bx);
        ull dA2 = pack2(dAv, dAv);
        ull acca = 0ull, accb = 0ull;
        #pragma unroll
        for (int i = 0; i < 8; i += 2) {
            hr2[i]     = fma2(dA2, hr2[i],     mul2(bx2, B2[i]));
            hr2[i + 1] = fma2(dA2, hr2[i + 1], mul2(bx2, B2[i + 1]));
            acca = fma2(hr2[i],     C2[i],     acca);
            accb = fma2(hr2[i + 1], C2[i + 1], accb);
        }
        ull accp = add2(acca, accb);
        float a0, a1; unpack2(accp, a0, a1);
        float acc = a0 + a1;
        acc += __shfl_xor_sync(0xffffffffu, acc, 1);
        acc += __shfl_xor_sync(0xffffffffu, acc, 2);
        if (q == 0) yout[(size_t)t * DINNER + h * 64 + p] = fmaf(Dp, xp, acc);
        if (tid == 0) g_cum[(size_t)idx * SEQ + s] = cum;
    }

    float* st = g_state + ((size_t)idx * NC + chunk) * 4096 + tid * 16;
    #pragma unroll
    for (int i = 0; i < 8; i++) {
        float x0, x1; unpack2(hr2[i], x0, x1);
        st[2 * i] = x0; st[2 * i + 1] = x1;
    }
}

// ---------------- scan pass C: inline combine + correction ----------------
__global__ __launch_bounds__(256) void scanC_kernel() {
    int h = blockIdx.x, b = blockIdx.y;
    int dir = blockIdx.z / (NC - 1), chunk = blockIdx.z % (NC - 1) + 1;
    int idx = (dir * BSZ + b) * NHEADS + h;
    const float* xbc  = g_xBC + (size_t)(dir * NTOK + b * SEQ) * CONVDIM;
    float*       yout = g_y   + (size_t)(dir * NTOK + b * SEQ) * DINNER;
    int tid = threadIdx.x;
    int p = tid >> 2, q = tid & 3, nbase = q * 16;
    int s0 = chunk * LC;

    __shared__ float scum[LC];
    __shared__ __align__(16) float sC[2][64];

    for (int i = tid; i < LC; i += 256)
        scum[i] = g_cum[(size_t)idx * SEQ + s0 + i];

    float hin[16];
    #pragma unroll
    for (int i = 0; i < 16; i++) hin[i] = 0.f;
    for (int j = 0; j < chunk; j++) {
        float P = g_cum[(size_t)idx * SEQ + j * LC + LC - 1];
        const float4* L = (const float4*)(g_state + ((size_t)idx * NC + j) * 4096 + tid * 16);
        #pragma unroll
        for (int i = 0; i < 4; i++) {
            float4 l = L[i];
            hin[4 * i]     = fmaf(P, hin[4 * i],     l.x);
            hin[4 * i + 1] = fmaf(P, hin[4 * i + 1], l.y);
            hin[4 * i + 2] = fmaf(P, hin[4 * i + 2], l.z);
            hin[4 * i + 3] = fmaf(P, hin[4 * i + 3], l.w);
        }
    }

    auto gloadC = [&](int s) -> float {
        int t = dir ? (SEQ - 1 - s) : s;
        if (tid < 64) return xbc[(size_t)t * CONVDIM + DINNER + DSTATE + tid];
        return 0.f;
    };

    float staged = gloadC(s0);

    for (int sl = 0; sl < LC; sl++) {
        int s = s0 + sl;
        int t = dir ? (SEQ - 1 - s) : s;
        int buf = sl & 1;
        if (tid < 64) sC[buf][tid] = staged;
        __syncthreads();
        if (sl + 1 < LC) staged = gloadC(s + 1);

        const float* Cv = &sC[buf][nbase];
        float acc = 0.f;
        #pragma unroll
        for (int i = 0; i < 16; i++) acc = fmaf(Cv[i], hin[i], acc);
        acc += __shfl_xor_sync(0xffffffffu, acc, 1);
        acc += __shfl_xor_sync(0xffffffffu, acc, 2);
        if (q == 0) {
            float* yp = &yout[(size_t)t * DINNER + h * 64 + p];
            *yp = fmaf(scum[sl], acc, *yp);
        }
    }
}

// ---------------- gate with SiLU(z), per-direction RMSNorm, sum dirs (fp16 out) ----------------
__global__ void gate_rms_kernel(const float* __restrict__ norm_w) {
    int row = blockIdx.x;
    __shared__ float gf[DINNER];
    __shared__ float gb[DINNER];
    const float* zr = g_zx + (size_t)row * DINPROJ;
    const float* yf = g_y  + (size_t)row * DINNER;
    const float* yb = g_y  + (size_t)(NTOK + row) * DINNER;
    float ssf = 0.f, ssb = 0.f;
    for (int c = threadIdx.x; c < DINNER; c += 256) {
        float zc = zr[c];
        float sz = zc / (1.f + expf(-zc));
        float a  = yf[c] * sz;
        float bb = yb[c] * sz;
        gf[c] = a; gb[c] = bb;
        ssf += a * a; ssb += bb * bb;
    }
    blockReduce2_256(ssf, ssb);
    float rf = rsqrtf(ssf / DINNER + LN_EPS);
    float rb = rsqrtf(ssb / DINNER + LN_EPS);
    __half* orow = g_gsumh + (size_t)row * DINNER;
    for (int c = threadIdx.x; c < DINNER; c += 256)
        orow[c] = __float2half((gf[c] * rf + gb[c] * rb) * norm_w[c]);
}

// ---------------- launch ----------------
extern "C" void kernel_launch(void* const* d_in, const int* in_sizes, int n_in,
                              void* d_out, int out_size) {
    const float* x         = (const float*)d_in[0];
    const float* in_proj_w = (const float*)d_in[1];
    const float* conv_w    = (const float*)d_in[2];
    const float* conv_b    = (const float*)d_in[3];
    const float* dt_bias   = (const float*)d_in[4];
    const float* A_log     = (const float*)d_in[5];
    const float* D_param   = (const float*)d_in[6];
    const float* norm_w    = (const float*)d_in[7];
    const float* out_proj_w= (const float*)d_in[8];
    const float* ln1_w     = (const float*)d_in[9];
    const float* ln1_b     = (const float*)d_in[10];
    const float* ln2_w     = (const float*)d_in[11];
    const float* ln2_b     = (const float*)d_in[12];
    const float* ff_w1     = (const float*)d_in[13];
    const float* ff_b1     = (const float*)d_in[14];
    const float* ff_w2     = (const float*)d_in[15];
    const float* ff_b2     = (const float*)d_in[16];
    float* out = (float*)d_out;

    void *p_zx, *p_xnh, *p_gsumh, *p_mh, *p_ff1h;
    void *p_wi, *p_wo, *p_w1, *p_w2, *p_part;
    cudaGetSymbolAddress(&p_zx,    g_zx);
    cudaGetSymbolAddress(&p_part,  g_part);
    cudaGetSymbolAddress(&p_xnh,   g_xnh);
    cudaGetSymbolAddress(&p_gsumh, g_gsumh);
    cudaGetSymbolAddress(&p_mh,    g_mh);
    cudaGetSymbolAddress(&p_ff1h,  g_ff1h);
    cudaGetSymbolAddress(&p_wi,    g_w_inproj_h);
    cudaGetSymbolAddress(&p_wo,    g_w_outproj_h);
    cudaGetSymbolAddress(&p_w1,    g_w_ff1_h);
    cudaGetSymbolAddress(&p_w2,    g_w_ff2_h);

    const int smemG = NSTAGE * (128 + 128) * BKW * sizeof(__half);   // 96 KB
    cudaFuncSetAttribute((const void*)hgemm<128,128,4,2>,
                         cudaFuncAttributeMaxDynamicSharedMemorySize, smemG);

    // 1) all weight conversions (16 elems/thread, MLP=4)
    {
        int n0 = DINPROJ * DMODEL / 16;
        int n1 = DMODEL * DINNER / 16;
        int n2 = DFF * DMODEL / 16;
        int n3 = DMODEL * DFF / 16;
        int tot = n0 + n1 + n2 + n3;
        f2h_all_kernel<<<(tot + 255) / 256, 256>>>(
            in_proj_w, (__half*)p_wi, n0,
            out_proj_w, (__half*)p_wo, n1,
            ff_w1, (__half*)p_w1, n2,
            ff_w2, (__half*)p_w2, n3);
    }

    // 2) LN1 -> fp16 xn
    ln_kernel<<<NTOK, 256>>>(x, ln1_w, ln1_b, (__half*)p_xnh, DMODEL);

    // 3) in_proj GEMM: 26x8 = 208 blocks
    hgemm<128,128,4,2><<<dim3((DINPROJ + 127) / 128, NTOK / 128), 256, smemG>>>(
        (const __half*)p_xnh, (const __half*)p_wi,
        NTOK, DINPROJ, DMODEL, (float*)p_zx, nullptr, nullptr, nullptr, 0);

    // 4) conv + SiLU (both directions) with fused dt/dA
    conv_silu_tile<<<dim3(CONVDIM / CC, SEQ / CT, BSZ), 256>>>(conv_w, conv_b, dt_bias, A_log);

    // 5) chunked selective scan
    scanA_kernel<<<dim3(NHEADS, BSZ, 2 * NC), 256>>>(D_param);
    scanC_kernel<<<dim3(NHEADS, BSZ, 2 * (NC - 1)), 256>>>();

    // 6) gate + RMSNorm + direction-sum -> fp16
    gate_rms_kernel<<<NTOK, 256>>>(norm_w);

    // 7) out_proj GEMM split-K x6 -> partials: 6x8x6 = 288 blocks
    hgemm<128,128,4,2><<<dim3(DMODEL / 128, NTOK / 128, KSPLIT), 256, smemG>>>(
        (const __half*)p_gsumh, (const __half*)p_wo,
        NTOK, DMODEL, DINNER, (float*)p_part, nullptr, nullptr, nullptr, 0);

    // 8) reduce partials + LN2 -> fp16 m
    reduce_ln2_kernel<<<NTOK, 256>>>(ln2_w, ln2_b);

    // 9) FF1 + bias + GELU -> fp16: 24x8 = 192 blocks
    hgemm<128,128,4,2><<<dim3(DFF / 128, NTOK / 128), 256, smemG>>>(
        (const __half*)p_mh, (const __half*)p_w1,
        NTOK, DFF, DMODEL, nullptr, (__half*)p_ff1h, ff_b1, nullptr, 1);

    // 10) FF2 split-K x6 -> partials: 288 blocks
    hgemm<128,128,4,2><<<dim3(DMODEL / 128, NTOK / 128, KSPLIT), 256, smemG>>>(
        (const __half*)p_ff1h, (const __half*)p_w2,
        NTOK, DMODEL, DFF, (float*)p_part, nullptr, nullptr, nullptr, 0);

    // 11) reduce partials + bias + residual -> out
    reduce_out_kernel<<<(NTOK * DMODEL / 4 + 255) / 256, 256>>>(ff_b2, x, out);
}